// round 5
// baseline (speedup 1.0000x reference)
#include <cuda_runtime.h>
#include <cuda_bf16.h>
#include <cstdint>
#include <cfloat>

// Problem constants: z (2,64,8,64,64), embedding (4096,64)
#define BATCH 2
#define CH 64
#define SPA 32768
#define NTOK 65536
#define KCODE 4096
#define OUT_ELEMS 4194304
#define KEXT 192            // bf16x3 split K: tokens [hi|hi|lo] x codes [hi|lo|hi]
#define GAP_TAU 0.07f       // > idx-embed quantization (0.031) + bf16x3 err (1e-4)

// smem layout for kB (bytes): padded row stride 400B (200 bf16) => ldmatrix conflict-free
#define RS 400
#define SMA 0
#define SMB0 51200
#define SMB1 102400
#define SMRED 153600
#define SMTOT (153600 + 3 * 512 * 4)   // + sb1e/sb1v/sb2v [4][128] floats

typedef unsigned long long ull;

// -------- static device scratch (no cudaMalloc allowed) --------
__device__ float g_tT[CH * NTOK];                        // pre-conv out, [c][n] fp32
__device__ __align__(16) __nv_bfloat16 g_tp[NTOK * KEXT];    // tokens split, row-major
__device__ __align__(16) __nv_bfloat16 g_ep[KCODE * KEXT];   // codes split, row-major
__device__ int   g_idx[NTOK];
__device__ float g_e2[KCODE];
__device__ float g_pe[KCODE * CH];                       // emb @ post_w^T + post_b
__device__ float g_part[256];
__device__ int   g_nflag;
__device__ int   g_flag[NTOK];

// ======================= helpers =======================
__device__ __forceinline__ uint32_t smem_u32(const void* p) {
    uint32_t a;
    asm("{ .reg .u64 t; cvta.to.shared.u64 t, %1; cvt.u32.u64 %0, t; }" : "=r"(a) : "l"(p));
    return a;
}
__device__ __forceinline__ void cpa16(uint32_t dst, const void* src) {
    asm volatile("cp.async.cg.shared.global [%0], [%1], 16;" :: "r"(dst), "l"(src) : "memory");
}
#define CP_COMMIT() asm volatile("cp.async.commit_group;" ::: "memory")
#define CP_WAIT0()  asm volatile("cp.async.wait_group 0;" ::: "memory")
#define CP_WAIT1()  asm volatile("cp.async.wait_group 1;" ::: "memory")

__device__ __forceinline__ void ldsm4(uint32_t* r, uint32_t addr) {
    asm volatile("ldmatrix.sync.aligned.m8n8.x4.shared.b16 {%0,%1,%2,%3}, [%4];"
        : "=r"(r[0]), "=r"(r[1]), "=r"(r[2]), "=r"(r[3]) : "r"(addr));
}
__device__ __forceinline__ void mma16816(float* c, const uint32_t* a, const uint32_t* b) {
    asm volatile("mma.sync.aligned.m16n8k16.row.col.f32.bf16.bf16.f32 "
        "{%0,%1,%2,%3}, {%4,%5,%6,%7}, {%8,%9}, {%0,%1,%2,%3};"
        : "+f"(c[0]), "+f"(c[1]), "+f"(c[2]), "+f"(c[3])
        : "r"(a[0]), "r"(a[1]), "r"(a[2]), "r"(a[3]), "r"(b[0]), "r"(b[1]));
}
// (score & 0xFFFFF000) | k  -> float compare keeps idx in low mantissa bits
__device__ __forceinline__ float emb_idx(float s, uint32_t k) {
    uint32_t r;
    asm("lop3.b32 %0, %1, 0xFFFFF000, %2, 0xEA;" : "=r"(r) : "r"(__float_as_uint(s)), "r"(k));
    return __uint_as_float(r);
}

// stage 128 rows x 192 bf16 (row-major stride 192) into padded smem (stride RS)
__device__ __forceinline__ void stage_tile(const __nv_bfloat16* __restrict__ src,
                                           uint32_t dst, int tid) {
#pragma unroll
    for (int it = 0; it < 12; it++) {
        int idx = tid + it * 256;           // 3072 segs of 16B
        int row = idx / 24;
        int seg = idx - row * 24;
        cpa16(dst + row * RS + seg * 16, src + row * KEXT + seg * 8);
    }
}

// ============================================================================
// kP: pe = emb @ post_w^T + post_b ; e2 ; E' bf16 split rows [hi|lo|hi]
// ============================================================================
__global__ void kP(const float* __restrict__ emb,
                   const float* __restrict__ post_w,
                   const float* __restrict__ post_b) {
    __shared__ float wsm[64 * 65];
    __shared__ float esm[64];
    __shared__ float wred[2];
    int tid = threadIdx.x;
    if (tid == 0 && blockIdx.x == 0) g_nflag = 0;

    for (int i = tid; i < 4096; i += 64)
        wsm[(i >> 6) * 65 + (i & 63)] = post_w[i];
    float wb = post_b[tid];

    for (int kk = 0; kk < 16; kk++) {
        int k = blockIdx.x * 16 + kk;
        __syncthreads();
        float v = emb[k * 64 + tid];
        esm[tid] = v;
        __syncthreads();
        float acc = wb;
#pragma unroll
        for (int c = 0; c < 64; c++)
            acc = fmaf(esm[c], wsm[tid * 65 + c], acc);
        g_pe[k * 64 + tid] = acc;

        __nv_bfloat16 hi = __float2bfloat16(v);
        __nv_bfloat16 lo = __float2bfloat16(v - __bfloat162float(hi));
        g_ep[k * KEXT + tid]       = hi;
        g_ep[k * KEXT + 64 + tid]  = lo;
        g_ep[k * KEXT + 128 + tid] = hi;

        float sq = v * v;
#pragma unroll
        for (int off = 16; off; off >>= 1)
            sq += __shfl_xor_sync(0xffffffffu, sq, off);
        if ((tid & 31) == 0) wred[tid >> 5] = sq;
        __syncthreads();
        if (tid == 0) g_e2[k] = wred[0] + wred[1];
    }
}

// ============================================================================
// kA: pre-conv fp32 -> g_tT[c][n]; bf16 split rows -> g_tp [n][hi|hi|lo]
// ============================================================================
__global__ void __launch_bounds__(256) kA(const float* __restrict__ z,
                                          const float* __restrict__ pre_w,
                                          const float* __restrict__ pre_b) {
    extern __shared__ char dyn[];
    float* wsm = (float*)dyn;                        // 4096
    float* bsm = wsm + 4096;                         // 64
    __nv_bfloat16* shh = (__nv_bfloat16*)(bsm + 64); // [256][66]
    __nv_bfloat16* shl = shh + 256 * 66;             // [256][66]

    int tid = threadIdx.x;
    int n0 = blockIdx.x * 256;
    int n = n0 + tid;
    for (int i = tid; i < 4096; i += 256) wsm[i] = pre_w[i];
    if (tid < 64) bsm[tid] = pre_b[tid];

    int b = n >> 15;
    int s = n & 32767;
    const float* zp = z + (size_t)b * (CH * SPA) + s;
    float zr[64];
#pragma unroll
    for (int c = 0; c < 64; c++) zr[c] = zp[(size_t)c * SPA];
    __syncthreads();

    for (int o = 0; o < 64; o++) {
        float acc = bsm[o];
#pragma unroll
        for (int c = 0; c < 64; c++)
            acc = fmaf(zr[c], wsm[o * 64 + c], acc);
        g_tT[(size_t)o * NTOK + n] = acc;
        __nv_bfloat16 hi = __float2bfloat16(acc);
        __nv_bfloat16 lo = __float2bfloat16(acc - __bfloat162float(hi));
        shh[tid * 66 + o] = hi;
        shl[tid * 66 + o] = lo;
    }
    __syncthreads();

    uint32_t* gout = (uint32_t*)g_tp;
    for (int ii = tid; ii < 256 * 96; ii += 256) {
        int row = ii / 96;
        int u = ii - row * 96;
        int c2 = u * 2;
        uint32_t v;
        if (c2 < 64)       v = *(const uint32_t*)&shh[row * 66 + c2];
        else if (c2 < 128) v = *(const uint32_t*)&shh[row * 66 + (c2 - 64)];
        else               v = *(const uint32_t*)&shl[row * 66 + (c2 - 128)];
        gout[(size_t)(n0 + row) * 96 + u] = v;
    }
}

// ============================================================================
// kB v4: HMMA (mma.sync m16n8k16 bf16) distance GEMM + fused argmin epilogue.
// 512 CTAs x 256 thr; 128 tokens/CTA; 32 chunks of 128 codes, double-buffered.
// Warp grid 2(M) x 4(N); warp tile 64x32; per-thread 64 fp32 accumulators.
// Argmin: FMNMX on scores with code idx embedded in low 12 mantissa bits;
// exact-value (b1,b2) tracked separately; gap < GAP_TAU -> exact rescore in kR.
// ============================================================================
__global__ void __launch_bounds__(256, 1) kB() {
    extern __shared__ __align__(128) char sm[];
    uint32_t smb = smem_u32(sm);
    float* sb1e = (float*)(sm + SMRED);      // [4][128]
    float* sb1v = sb1e + 512;
    float* sb2v = sb1v + 512;

    int tid = threadIdx.x;
    int lane = tid & 31;
    int wid = tid >> 5;
    int wm = wid >> 2;                       // 0..1 -> rows wm*64
    int wn = wid & 3;                        // 0..3 -> cols wn*32
    int n0 = blockIdx.x * 128;

    // prologue: A + B0 in group0, B1 in group1
    stage_tile(g_tp + (size_t)n0 * KEXT, smb + SMA, tid);
    stage_tile(g_ep, smb + SMB0, tid);
    CP_COMMIT();
    stage_tile(g_ep + (size_t)128 * KEXT, smb + SMB1, tid);
    CP_COMMIT();

    // ldmatrix address bases
    uint32_t aBase = smb + SMA + (uint32_t)(wm * 64 + (lane & 15)) * RS + ((lane >> 4) << 4);
    uint32_t bOff  = (uint32_t)(wn * 32 + ((lane >> 4) << 3) + (lane & 7)) * RS
                   + (((lane >> 3) & 1) << 4);

    float b1e[8], b1v[8], b2v[8];
#pragma unroll
    for (int r = 0; r < 8; r++) { b1e[r] = FLT_MAX; b1v[r] = FLT_MAX; b2v[r] = FLT_MAX; }

    int colq = wn * 32 + 2 * (lane & 3);

    for (int i = 0; i < 32; i++) {
        if (i < 31) { CP_WAIT1(); } else { CP_WAIT0(); }
        __syncthreads();

        uint32_t bBase = smb + ((i & 1) ? SMB1 : SMB0) + bOff;

        float e2r[4][2];
        uint32_t kr[4];
#pragma unroll
        for (int nt = 0; nt < 4; nt++) {
            int k0 = i * 128 + colq + nt * 8;
            kr[nt] = (uint32_t)k0;
            e2r[nt][0] = __ldg(&g_e2[k0]);
            e2r[nt][1] = __ldg(&g_e2[k0 + 1]);
        }

        float acc[4][4][4];
#pragma unroll
        for (int mt = 0; mt < 4; mt++)
#pragma unroll
            for (int nt = 0; nt < 4; nt++)
#pragma unroll
                for (int q = 0; q < 4; q++) acc[mt][nt][q] = 0.0f;

#pragma unroll
        for (int ks = 0; ks < 12; ks++) {
            uint32_t af[4][4], bf[4][2];
#pragma unroll
            for (int mt = 0; mt < 4; mt++)
                ldsm4(af[mt], aBase + (uint32_t)(mt * 16 * RS) + (uint32_t)(ks * 32));
#pragma unroll
            for (int np = 0; np < 2; np++) {
                uint32_t r[4];
                ldsm4(r, bBase + (uint32_t)(np * 16 * RS) + (uint32_t)(ks * 32));
                bf[np * 2][0] = r[0]; bf[np * 2][1] = r[1];
                bf[np * 2 + 1][0] = r[2]; bf[np * 2 + 1][1] = r[3];
            }
#pragma unroll
            for (int mt = 0; mt < 4; mt++)
#pragma unroll
                for (int nt = 0; nt < 4; nt++)
                    mma16816(acc[mt][nt], af[mt], bf[nt]);
        }

        // fused epilogue: score = e2 - 2*dot
#pragma unroll
        for (int mt = 0; mt < 4; mt++) {
#pragma unroll
            for (int nt = 0; nt < 4; nt++) {
                float s00 = fmaf(acc[mt][nt][0], -2.0f, e2r[nt][0]);
                float s01 = fmaf(acc[mt][nt][1], -2.0f, e2r[nt][1]);
                float s10 = fmaf(acc[mt][nt][2], -2.0f, e2r[nt][0]);
                float s11 = fmaf(acc[mt][nt][3], -2.0f, e2r[nt][1]);
                int r0 = mt * 2, r1 = mt * 2 + 1;
                uint32_t k0 = kr[nt], k1 = kr[nt] + 1;
                // rowslot r0
                b1e[r0] = fminf(b1e[r0], emb_idx(s00, k0));
                b2v[r0] = fminf(b2v[r0], fmaxf(b1v[r0], s00));
                b1v[r0] = fminf(b1v[r0], s00);
                b1e[r0] = fminf(b1e[r0], emb_idx(s01, k1));
                b2v[r0] = fminf(b2v[r0], fmaxf(b1v[r0], s01));
                b1v[r0] = fminf(b1v[r0], s01);
                // rowslot r1
                b1e[r1] = fminf(b1e[r1], emb_idx(s10, k0));
                b2v[r1] = fminf(b2v[r1], fmaxf(b1v[r1], s10));
                b1v[r1] = fminf(b1v[r1], s10);
                b1e[r1] = fminf(b1e[r1], emb_idx(s11, k1));
                b2v[r1] = fminf(b2v[r1], fmaxf(b1v[r1], s11));
                b1v[r1] = fminf(b1v[r1], s11);
            }
        }

        __syncthreads();                 // all warps done reading this B buffer
        if (i + 2 < 32) {
            stage_tile(g_ep + (size_t)(i + 2) * 128 * KEXT,
                       smb + ((i & 1) ? SMB1 : SMB0), tid);
            CP_COMMIT();
        }
    }

    // quad merge (lanes holding the same rows: lane ^ 1, lane ^ 2)
#pragma unroll
    for (int off = 1; off <= 2; off <<= 1) {
#pragma unroll
        for (int r = 0; r < 8; r++) {
            float o1e = __shfl_xor_sync(0xffffffffu, b1e[r], off);
            float o1v = __shfl_xor_sync(0xffffffffu, b1v[r], off);
            float o2v = __shfl_xor_sync(0xffffffffu, b2v[r], off);
            b2v[r] = fminf(fminf(b2v[r], o2v), fmaxf(b1v[r], o1v));
            b1v[r] = fminf(b1v[r], o1v);
            b1e[r] = fminf(b1e[r], o1e);
        }
    }
    if ((lane & 3) == 0) {
#pragma unroll
        for (int r = 0; r < 8; r++) {
            int row = wm * 64 + (r >> 1) * 16 + (r & 1) * 8 + (lane >> 2);
            sb1e[wn * 128 + row] = b1e[r];
            sb1v[wn * 128 + row] = b1v[r];
            sb2v[wn * 128 + row] = b2v[r];
        }
    }
    __syncthreads();
    if (tid < 128) {
        float f1e = FLT_MAX, f1v = FLT_MAX, f2v = FLT_MAX;
#pragma unroll
        for (int w = 0; w < 4; w++) {
            float e = sb1e[w * 128 + tid];
            float v = sb1v[w * 128 + tid];
            float v2 = sb2v[w * 128 + tid];
            f2v = fminf(fminf(f2v, v2), fmaxf(f1v, v));
            f1v = fminf(f1v, v);
            f1e = fminf(f1e, e);
        }
        int idx = (int)(__float_as_uint(f1e) & 0xFFFu);
        g_idx[n0 + tid] = idx;
        if (f2v - f1v < GAP_TAU) {
            int p = atomicAdd(&g_nflag, 1);
            g_flag[p] = n0 + tid;
        }
    }
}

// ============================================================================
// kR: exact fp32 rescore of flagged tokens (bit-identical to the R2 math),
// 8 tokens per block sharing the codebook scan.
// ============================================================================
__global__ void __launch_bounds__(256) kR(const float* __restrict__ emb) {
    __shared__ float tv[8][64];
    __shared__ int tn[8];
    __shared__ float rv[256];
    __shared__ int ri[256];
    int tid = threadIdx.x;
    int cnt = g_nflag;
    int nblk = (cnt + 7) >> 3;

    for (int blk = blockIdx.x; blk < nblk; blk += gridDim.x) {
        int base = blk * 8;
        __syncthreads();
        if (tid < 8) tn[tid] = (base + tid < cnt) ? g_flag[base + tid] : -1;
        __syncthreads();
        {
            int tt = tid >> 5;          // 8 tokens x 32 threads? no: 256 thr -> 8x(2 ch each)
        }
        // load token vectors: 8*64 = 512 elems, 2 per thread
        for (int ii = tid; ii < 512; ii += 256) {
            int tt = ii >> 6, c = ii & 63;
            int n = (tn[tt] >= 0) ? tn[tt] : tn[0];
            tv[tt][c] = g_tT[(size_t)c * NTOK + n];
        }
        __syncthreads();

        float best[8];
        int bidx[8];
#pragma unroll
        for (int t = 0; t < 8; t++) { best[t] = FLT_MAX; bidx[t] = 0x7fffffff; }

        for (int c16 = 0; c16 < 16; c16++) {
            int k = c16 * 256 + tid;
            const float4* er = (const float4*)(emb + (size_t)k * 64);
            float d[8];
#pragma unroll
            for (int t = 0; t < 8; t++) d[t] = 0.0f;
#pragma unroll
            for (int c4 = 0; c4 < 16; c4++) {
                float4 ev = er[c4];
                int c = c4 * 4;
#pragma unroll
                for (int t = 0; t < 8; t++) {
                    d[t] = fmaf(tv[t][c + 0], ev.x, d[t]);
                    d[t] = fmaf(tv[t][c + 1], ev.y, d[t]);
                    d[t] = fmaf(tv[t][c + 2], ev.z, d[t]);
                    d[t] = fmaf(tv[t][c + 3], ev.w, d[t]);
                }
            }
            float e2k = g_e2[k];
#pragma unroll
            for (int t = 0; t < 8; t++) {
                float s = fmaf(d[t], -2.0f, e2k);
                if (s < best[t] || (s == best[t] && k < bidx[t])) { best[t] = s; bidx[t] = k; }
            }
        }

        for (int t = 0; t < 8; t++) {
            if (tn[t] < 0) break;       // uniform across block
            rv[tid] = best[t];
            ri[tid] = bidx[t];
            __syncthreads();
#pragma unroll
            for (int st = 128; st > 0; st >>= 1) {
                if (tid < st) {
                    float v2 = rv[tid + st]; int i2 = ri[tid + st];
                    if (v2 < rv[tid] || (v2 == rv[tid] && i2 < ri[tid])) {
                        rv[tid] = v2; ri[tid] = i2;
                    }
                }
                __syncthreads();
            }
            if (tid == 0) g_idx[tn[t]] = ri[0];
            __syncthreads();
        }
    }
}

// ============================================================================
// kC: loss partials + post-conv (pe gather) + index output
// ============================================================================
__global__ void __launch_bounds__(256) kC(const float* __restrict__ emb,
                                          float* __restrict__ dout) {
    int tid = threadIdx.x;
    int n = blockIdx.x * 256 + tid;
    int idx = g_idx[n];

    const float4* er4 = (const float4*)(emb + (size_t)idx * 64);
    float lsum = 0.0f;
#pragma unroll
    for (int c4 = 0; c4 < 16; c4++) {
        float4 e4 = er4[c4];
        int c = c4 * 4;
        float d0 = e4.x - g_tT[(size_t)(c + 0) * NTOK + n];
        float d1 = e4.y - g_tT[(size_t)(c + 1) * NTOK + n];
        float d2 = e4.z - g_tT[(size_t)(c + 2) * NTOK + n];
        float d3 = e4.w - g_tT[(size_t)(c + 3) * NTOK + n];
        lsum = fmaf(d0, d0, lsum);
        lsum = fmaf(d1, d1, lsum);
        lsum = fmaf(d2, d2, lsum);
        lsum = fmaf(d3, d3, lsum);
    }

    int b = n >> 15;
    int s = n & 32767;
    float* op = dout + (size_t)b * (CH * SPA) + s;
    const float4* pr4 = (const float4*)(g_pe + (size_t)idx * 64);
#pragma unroll
    for (int o4 = 0; o4 < 16; o4++) {
        float4 p = pr4[o4];
        int o = o4 * 4;
        op[(size_t)(o + 0) * SPA] = p.x;
        op[(size_t)(o + 1) * SPA] = p.y;
        op[(size_t)(o + 2) * SPA] = p.z;
        op[(size_t)(o + 3) * SPA] = p.w;
    }

    dout[OUT_ELEMS + 2 + n] = (float)idx;

    __shared__ float red[256];
    red[tid] = lsum;
    __syncthreads();
#pragma unroll
    for (int st = 128; st > 0; st >>= 1) {
        if (tid < st) red[tid] += red[tid + st];
        __syncthreads();
    }
    if (tid == 0) g_part[blockIdx.x] = red[0];
}

// ============================================================================
__global__ void kD(float* __restrict__ dout) {
    __shared__ float red[256];
    int tid = threadIdx.x;
    red[tid] = g_part[tid];
    __syncthreads();
#pragma unroll
    for (int st = 128; st > 0; st >>= 1) {
        if (tid < st) red[tid] += red[tid + st];
        __syncthreads();
    }
    if (tid == 0) {
        float m = red[0] / (float)OUT_ELEMS;
        dout[OUT_ELEMS]     = m;   // codebook_loss
        dout[OUT_ELEMS + 1] = m;   // commitment_loss (same forward value)
    }
}

// ============================================================================
extern "C" void kernel_launch(void* const* d_in, const int* in_sizes, int n_in,
                              void* d_out, int out_size) {
    const float* z      = (const float*)d_in[0];
    const float* emb    = (const float*)d_in[1];
    const float* pre_w  = (const float*)d_in[2];
    const float* pre_b  = (const float*)d_in[3];
    const float* post_w = (const float*)d_in[4];
    const float* post_b = (const float*)d_in[5];
    float* dout = (float*)d_out;

    const int shA = (4096 + 64) * 4 + 2 * 256 * 66 * 2;   // 84224
    cudaFuncSetAttribute(kA, cudaFuncAttributeMaxDynamicSharedMemorySize, shA);
    cudaFuncSetAttribute(kB, cudaFuncAttributeMaxDynamicSharedMemorySize, SMTOT);

    kP<<<KCODE / 16, 64>>>(emb, post_w, post_b);
    kA<<<NTOK / 256, 256, shA>>>(z, pre_w, pre_b);
    kB<<<NTOK / 128, 256, SMTOT>>>();
    kR<<<128, 256>>>(emb);
    kC<<<NTOK / 256, 256>>>(emb, dout);
    kD<<<1, 256>>>(dout);
}